// round 5
// baseline (speedup 1.0000x reference)
#include <cuda_runtime.h>
#include <cuda_bf16.h>
#include <cstdint>

#define B_    256
#define T_    512
#define IN_   64
#define H_    1024
#define OUT_  128
#define NCTA  128
#define NKC   68                      // K chunks of 16: 64 (h) + 4 (x_t) = 17 groups of 4
#define HBUF  (16 * 64 * 2 * 32)      // uint4s per h buffer: [mt][kc][hl][lane]
#define AR_BYTES    65536             // A ring: 4 groups x 4 chunks x 4KB
#define B_BYTES     (NKC * 4 * 2 * 256)   // 139264
#define SMEM_BYTES  (AR_BYTES + B_BYTES)  // 204800

// ---------------- persistent device scratch ------------------------------
__device__ uint4 g_hA[2 * HBUF];                     // ping-pong h, A-frag packed
__device__ uint4 g_xp[(size_t)T_ * 16 * 4 * 2 * 32]; // x, A-frag packed per t
__device__ float g_hf[B_ * H_];                      // final h, plain fp32
__device__ unsigned g_bar_count;
__device__ volatile unsigned g_bar_gen;

// ---------------- helpers -------------------------------------------------
__device__ __forceinline__ uint32_t smem_u32(const void* p) {
    uint32_t a;
    asm("{ .reg .u64 t; cvta.to.shared.u64 t, %1; cvt.u32.u64 %0, t; }"
        : "=r"(a) : "l"(p));
    return a;
}

__device__ __forceinline__ uint32_t pk(float a, float b) {
    __nv_bfloat162 t = __floats2bfloat162_rn(a, b);
    return *reinterpret_cast<uint32_t*>(&t);
}

__device__ __forceinline__ void lds64(uint32_t* r, uint32_t a) {
    asm("ld.shared.v2.b32 {%0,%1}, [%2];" : "=r"(r[0]), "=r"(r[1]) : "r"(a));
}

__device__ __forceinline__ void lds128(uint32_t* r, uint32_t a) {
    asm("ld.shared.v4.b32 {%0,%1,%2,%3}, [%4];"
        : "=r"(r[0]), "=r"(r[1]), "=r"(r[2]), "=r"(r[3]) : "r"(a));
}

__device__ __forceinline__ void cp16(uint32_t dst, const void* src) {
    asm volatile("cp.async.cg.shared.global [%0], [%1], 16;"
                 :: "r"(dst), "l"(src) : "memory");
}

__device__ __forceinline__ void mma16816(float* c, const uint32_t* a, const uint32_t* b) {
    asm("mma.sync.aligned.m16n8k16.row.col.f32.bf16.bf16.f32 "
        "{%0,%1,%2,%3}, {%4,%5,%6,%7}, {%8,%9}, {%0,%1,%2,%3};"
        : "+f"(c[0]), "+f"(c[1]), "+f"(c[2]), "+f"(c[3])
        : "r"(a[0]), "r"(a[1]), "r"(a[2]), "r"(a[3]), "r"(b[0]), "r"(b[1]));
}

__device__ __forceinline__ void grid_sync() {
    __syncthreads();
    if (threadIdx.x == 0) {
        __threadfence();
        unsigned gen = g_bar_gen;
        if (atomicAdd(&g_bar_count, 1u) == NCTA - 1u) {
            atomicExch(&g_bar_count, 0u);
            __threadfence();
            g_bar_gen = gen + 1u;
        } else {
            while (g_bar_gen == gen) { }
        }
        __threadfence();
    }
    __syncthreads();
}

// ---------------- pack x into A-fragment layout (one-time) ----------------
__global__ void pack_x(const float* __restrict__ x, uint4* __restrict__ xp) {
    int id = blockIdx.x * (blockDim.x >> 5) + (threadIdx.x >> 5);
    int l  = threadIdx.x & 31;
    if (id >= T_ * 16 * 4) return;
    int t = id >> 6, mt = (id >> 2) & 15, kcx = id & 3;
    int b0 = mt * 16 + (l >> 2), b1 = b0 + 8;
    int i0 = kcx * 16 + 2 * (l & 3);
    const float* x0 = x + ((size_t)b0 * T_ + t) * IN_;
    const float* x1 = x + ((size_t)b1 * T_ + t) * IN_;
    float v00 = x0[i0], v01 = x0[i0 + 1], v02 = x0[i0 + 8], v03 = x0[i0 + 9];
    float v10 = x1[i0], v11 = x1[i0 + 1], v12 = x1[i0 + 8], v13 = x1[i0 + 9];
    uint4 hi4, lo4;
    hi4.x = pk(v00, v01); hi4.y = pk(v10, v11);
    hi4.z = pk(v02, v03); hi4.w = pk(v12, v13);
    float r00 = v00 - __bfloat162float(__float2bfloat16(v00));
    float r01 = v01 - __bfloat162float(__float2bfloat16(v01));
    float r02 = v02 - __bfloat162float(__float2bfloat16(v02));
    float r03 = v03 - __bfloat162float(__float2bfloat16(v03));
    float r10 = v10 - __bfloat162float(__float2bfloat16(v10));
    float r11 = v11 - __bfloat162float(__float2bfloat16(v11));
    float r12 = v12 - __bfloat162float(__float2bfloat16(v12));
    float r13 = v13 - __bfloat162float(__float2bfloat16(v13));
    lo4.x = pk(r00, r01); lo4.y = pk(r10, r11);
    lo4.z = pk(r02, r03); lo4.w = pk(r12, r13);
    size_t base = (size_t)id * 64 + l;
    xp[base] = hi4;
    xp[base + 32] = lo4;
}

// ---------------- persistent mma.sync RNN --------------------------------
// 128 CTAs x 256 threads (8 warps, wm 0-3 x wn 0-1). CTA tile M64 x N32;
// warp tile m16 x n16. A staged through smem via cp.async group pipeline.
__global__ void __launch_bounds__(256, 1) rnn_mma(
    float* __restrict__ out, const float* __restrict__ Wh,
    const float* __restrict__ Wx, const float* __restrict__ Wo,
    const uint4* __restrict__ xp, uint4* __restrict__ hA,
    float* __restrict__ hf)
{
    extern __shared__ __align__(16) uint8_t smem[];
    const int tid = threadIdx.x, l = tid & 31;
    const int wid = tid >> 5, wm = wid >> 1, wn = wid & 1;
    const int bid = blockIdx.x;
    const int m0 = (bid >> 5) << 6;        // batch tile: 4 x 64
    const int n0 = (bid & 31) << 5;        // hidden tile: 32 x 32
    const uint32_t sA = smem_u32(smem);    // A ring: 64 KB
    const uint32_t sB = sA + AR_BYTES;     // B slice: 136 KB

    // ---- one-time: pack B slice (rows n0..n0+31 of [Wh | Wx]) into smem ----
    for (int e = tid; e < 32 * 1088; e += 256) {
        int nl = e / 1088, k = e - nl * 1088;
        float v = (k < 1024) ? Wh[(size_t)(n0 + nl) * 1024 + k]
                             : Wx[(size_t)(n0 + nl) * 64 + (k - 1024)];
        __nv_bfloat16 h = __float2bfloat16(v);
        __nv_bfloat16 lo = __float2bfloat16(v - __bfloat162float(h));
        int kc = k >> 4, fr = nl >> 3;
        int lane = ((nl & 7) << 2) | ((k & 7) >> 1);
        int w = (k >> 3) & 1, hb = k & 1;
        uint32_t off = (uint32_t)((kc * 4 + fr) * 2) * 256 + lane * 8 + w * 4 + hb * 2;
        *reinterpret_cast<__nv_bfloat16*>(smem + AR_BYTES + off) = h;
        *reinterpret_cast<__nv_bfloat16*>(smem + AR_BYTES + off + 256) = lo;
    }
    // zero h buffer 0 (h_{-1} = 0)
    {
        uint4 z = make_uint4(0, 0, 0, 0);
        for (int i = bid * 256 + tid; i < HBUF; i += NCTA * 256) hA[i] = z;
    }
    grid_sync();

    const int mtgb = m0 >> 4;              // first global m16 tile of this CTA
    const int mtg  = mtgb + wm;            // this warp's m16 tile
    const int kcd  = (n0 >> 4) + wn;       // epilogue dest kc (next-step A chunk)

    // per-thread cp.async role: mt tile, hi/lo, lane
    const int cmt = tid >> 6, chl = (tid >> 5) & 1, cln = tid & 31;

    for (int t = 0; t < T_; ++t) {
        const uint4* __restrict__ hcur = hA + (size_t)(t & 1) * HBUF;
        uint4* __restrict__ hnxt       = hA + (size_t)((t + 1) & 1) * HBUF;
        const uint4* __restrict__ xpt  = xp + (size_t)t * 4096;

        // issue one group (4 chunks) of A into ring slot g&3
        auto issue_group = [&](int g) {
            const int slot = g & 3;
            const uint32_t dbase = sA + slot * 16384 + cmt * 1024 + chl * 512 + cln * 16;
#pragma unroll
            for (int ch = 0; ch < 4; ++ch) {
                const int kc = g * 4 + ch;
                const uint4* src = (kc < 64)
                    ? hcur + ((size_t)((mtgb + cmt) * 64 + kc) * 2 + chl) * 32 + cln
                    : xpt  + ((size_t)((mtgb + cmt) * 4 + (kc - 64)) * 2 + chl) * 32 + cln;
                cp16(dbase + ch * 4096, src);
            }
            asm volatile("cp.async.commit_group;" ::: "memory");
        };

        float chh[2][4], chl_[2][4], clh[2][4];
#pragma unroll
        for (int f = 0; f < 2; ++f)
#pragma unroll
            for (int j = 0; j < 4; ++j)
                chh[f][j] = chl_[f][j] = clh[f][j] = 0.f;

        issue_group(0); issue_group(1); issue_group(2);

#pragma unroll 1
        for (int g = 0; g < 17; ++g) {
            if (g < 15)       asm volatile("cp.async.wait_group 2;" ::: "memory");
            else if (g == 15) asm volatile("cp.async.wait_group 1;" ::: "memory");
            else              asm volatile("cp.async.wait_group 0;" ::: "memory");
            __syncthreads();

            const uint32_t abase = sA + (g & 3) * 16384 + wm * 1024 + l * 16;
            const uint32_t bbase = sB + (uint32_t)(g * 4) * 2048 + wn * 1024 + l * 8;
#pragma unroll
            for (int ch = 0; ch < 4; ++ch) {
                uint32_t ah[4], al[4];
                lds128(ah, abase + ch * 4096);
                lds128(al, abase + ch * 4096 + 512);
                uint32_t bh0[2], bh1[2], bl0[2], bl1[2];
                const uint32_t ba = bbase + ch * 2048;
                lds64(bh0, ba);        lds64(bl0, ba + 256);
                lds64(bh1, ba + 512);  lds64(bl1, ba + 768);

                mma16816(chh[0],  ah, bh0);  mma16816(chh[1],  ah, bh1);
                mma16816(chl_[0], ah, bl0);  mma16816(chl_[1], ah, bl1);
                mma16816(clh[0],  al, bh0);  mma16816(clh[1],  al, bh1);
            }
            if (g + 3 <= 16) issue_group(g + 3);
        }

        // ---- epilogue: relu, bf16 split, store in next-step A-frag layout ----
        {
            float v[2][4], r[2][4];
#pragma unroll
            for (int f = 0; f < 2; ++f)
#pragma unroll
                for (int j = 0; j < 4; ++j) {
                    float s = chh[f][j] + chl_[f][j] + clh[f][j];
                    s = fmaxf(s, 0.f);
                    v[f][j] = s;
                    r[f][j] = s - __bfloat162float(__float2bfloat16(s));
                }
            uint4 hi4, lo4;
            hi4.x = pk(v[0][0], v[0][1]);  hi4.y = pk(v[0][2], v[0][3]);
            hi4.z = pk(v[1][0], v[1][1]);  hi4.w = pk(v[1][2], v[1][3]);
            lo4.x = pk(r[0][0], r[0][1]);  lo4.y = pk(r[0][2], r[0][3]);
            lo4.z = pk(r[1][0], r[1][1]);  lo4.w = pk(r[1][2], r[1][3]);
            uint4* dst = hnxt + ((size_t)(mtg * 64 + kcd) * 2) * 32 + l;
            dst[0]  = hi4;
            dst[32] = lo4;
            if (t == T_ - 1) {
                int r0 = mtg * 16 + (l >> 2);
                int c0 = n0 + wn * 16 + 2 * (l & 3);
                *(float2*)&hf[(size_t)r0 * H_ + c0]           = make_float2(v[0][0], v[0][1]);
                *(float2*)&hf[(size_t)(r0 + 8) * H_ + c0]     = make_float2(v[0][2], v[0][3]);
                *(float2*)&hf[(size_t)r0 * H_ + c0 + 8]       = make_float2(v[1][0], v[1][1]);
                *(float2*)&hf[(size_t)(r0 + 8) * H_ + c0 + 8] = make_float2(v[1][2], v[1][3]);
            }
        }
        grid_sync();
    }

    // ---- final: out[m][o] = sum_k h[m][k] * Wo[o][k]; 2 batch rows per CTA ---
    {
        float* sw = (float*)smem;                 // [128][129] padded
        float* sh = (float*)smem + 128 * 129;     // [2][1024]
        const int m = bid * 2;
        const int half = tid >> 7, o = tid & 127;
        for (int i = tid; i < 2 * H_; i += 256)
            sh[i] = hf[(size_t)(m + (i >> 10)) * H_ + (i & 1023)];
        float acc = 0.f;
        for (int k0 = 0; k0 < H_; k0 += 128) {
            __syncthreads();
            for (int i = tid; i < 128 * 128; i += 256) {
                int oo = i >> 7, kk = i & 127;
                sw[oo * 129 + kk] = Wo[(size_t)oo * H_ + k0 + kk];
            }
            __syncthreads();
#pragma unroll 8
            for (int kk = 0; kk < 128; ++kk)
                acc = fmaf(sh[half * H_ + k0 + kk], sw[o * 129 + kk], acc);
        }
        out[(size_t)(m + half) * OUT_ + o] = acc;
    }
}

// ---------------- launch --------------------------------------------------
extern "C" void kernel_launch(void* const* d_in, const int* in_sizes, int n_in,
                              void* d_out, int out_size) {
    (void)in_sizes; (void)n_in; (void)out_size;
    const float* x  = (const float*)d_in[0];
    const float* Wh = (const float*)d_in[1];
    const float* Wx = (const float*)d_in[2];
    const float* Wo = (const float*)d_in[3];
    float* out = (float*)d_out;

    uint4 *phA, *pxp;
    float* phf;
    cudaGetSymbolAddress((void**)&phA, g_hA);
    cudaGetSymbolAddress((void**)&pxp, g_xp);
    cudaGetSymbolAddress((void**)&phf, g_hf);

    pack_x<<<4096, 256>>>(x, pxp);

    cudaFuncSetAttribute(rnn_mma, cudaFuncAttributeMaxDynamicSharedMemorySize, SMEM_BYTES);
    rnn_mma<<<NCTA, 256, SMEM_BYTES>>>(out, Wh, Wx, Wo, pxp, phA, phf);
}